// round 16
// baseline (speedup 1.0000x reference)
#include <cuda_runtime.h>
#include <math.h>

#define B 8
#define NEV 100000
#define NPARAMS 4000000
#define EPSF 1.1920928955078125e-07f

// Twin accumulators, float2 per pixel (x=num, y=den).
#define ACCUM_F2 2785280
__device__ __align__(16) float2 g_accum [ACCUM_F2];
__device__ __align__(16) float2 g_accumB[ACCUM_F2 + 2];
__device__ float g_tref[B][2][2];

// Interleaved flow (fx,fy) per pixel
#define FI_TOT 696320
__device__ __align__(16) float2 g_fint[FI_TOT];
__device__ __constant__ int c_fioff[4]  = {0, 8192, 40960, 172032};
__device__ __constant__ int c_fioff4[5] = {0, 2048, 10240, 43008, 174080};

// Event sort: key = m*4096 + y*16 + (x>>4), 8192 buckets per batch.
#define NKEY 8192
#define HIST_TOT (B * NKEY)
__device__ int g_hist[HIST_TOT];     // zero at load; re-zeroed by k_post each call
__device__ int g_cursor[HIST_TOT];   // fully rewritten by prefix each call
__device__ __align__(16) int2 g_sev[B * NEV];   // sorted packed events

#define NB_SM 512
#define NB_WD 256
#define NB_ER 1024
#define NB_HZ 16
__device__ double g_part_sm[NB_SM];
__device__ double g_part_wd[NB_WD];
__device__ double g_part_er[NB_ER];
__device__ unsigned g_done;
__device__ unsigned g_cPfx;

__device__ __constant__ int c_loff[4] = {0, 32768, 163840, 688128};

// ---------------------------------------------------------------------------
__device__ __forceinline__ void red4(float2* addr, float a, float b, float c, float d) {
    asm volatile("red.global.add.v4.f32 [%0], {%1,%2,%3,%4};" ::
                 "l"(addr), "f"(a), "f"(b), "f"(c), "f"(d));
}
__device__ __forceinline__ void red2(float2* addr, float a, float b) {
    asm volatile("red.global.add.v2.f32 [%0], {%1,%2};" ::
                 "l"(addr), "f"(a), "f"(b));
}
__device__ __forceinline__ float rsqrt_approx(float x) {
    float r;
    asm("rsqrt.approx.f32 %0, %1;" : "=f"(r) : "f"(x));
    return r;
}
__device__ __forceinline__ unsigned ld_acquire(unsigned* p) {
    unsigned v;
    asm volatile("ld.acquire.gpu.u32 %0, [%1];" : "=r"(v) : "l"(p) : "memory");
    return v;
}
__device__ __forceinline__ void gate_wait(unsigned* c, unsigned target) {
    if (threadIdx.x == 0) {
        while (ld_acquire(c) < target) __nanosleep(128);
    }
    __syncthreads();
}
__device__ __forceinline__ void gate_arrive(unsigned* c) {
    __syncthreads();
    __threadfence();
    if (threadIdx.x == 0) atomicAdd(c, 1u);
}
__device__ __forceinline__ int ev_key(int b, int x, int y, int m) {
    return b * NKEY + m * 4096 + y * 16 + (x >> 4);
}

// ---------------------------------------------------------------------------
__device__ __forceinline__ double block_reduce(float acc) {
    __shared__ double swarp[8];
    for (int o = 16; o > 0; o >>= 1) acc += __shfl_down_sync(0xffffffffu, acc, o);
    int wid = threadIdx.x >> 5, lid = threadIdx.x & 31;
    if (lid == 0) swarp[wid] = (double)acc;
    __syncthreads();
    double s = 0.0;
    if (threadIdx.x == 0)
        for (int w = 0; w < 8; w++) s += swarp[w];
    return s;
}

// ---------------------------------------------------------------------------
// k_pre: zeroA(512) | zeroB(512) | FI(256) | tref(4) | hist(256)
// ---------------------------------------------------------------------------
#define PRE_Z 512
#define PRE_FI 256
#define PRE_HIST 256
#define PRE_NB (2 * PRE_Z + PRE_FI + 4 + PRE_HIST)   // 1540
__global__ void __launch_bounds__(256)
k_pre(const float* __restrict__ f0, const float* __restrict__ f1,
      const float* __restrict__ f2, const float* __restrict__ f3,
      const float* __restrict__ ts, const int* __restrict__ ps,
      const int* __restrict__ xs, const int* __restrict__ ys) {
    int bid = blockIdx.x, tid = threadIdx.x;
    if (bid < PRE_Z) {
        if (bid == 0 && tid == 0) { g_done = 0; g_cPfx = 0; }
        float4* p = (float4*)g_accum;
        const int n = ACCUM_F2 / 2;
        for (int i = bid * 256 + tid; i < n; i += PRE_Z * 256)
            p[i] = make_float4(0.f, 0.f, 0.f, 0.f);
    } else if (bid < 2 * PRE_Z) {
        float4* p = (float4*)g_accumB;
        const int n = (ACCUM_F2 + 2) / 2;
        for (int i = (bid - PRE_Z) * 256 + tid; i < n; i += PRE_Z * 256)
            p[i] = make_float4(0.f, 0.f, 0.f, 0.f);
    } else if (bid < 2 * PRE_Z + PRE_FI) {
        const float* fl[4] = {f0, f1, f2, f3};
        const int n = c_fioff4[4];
        for (int i = (bid - 2 * PRE_Z) * 256 + tid; i < n; i += PRE_FI * 256) {
            int l = (i < c_fioff4[1]) ? 0 : (i < c_fioff4[2]) ? 1
                  : (i < c_fioff4[3]) ? 2 : 3;
            int rem = i - c_fioff4[l];
            int lg4 = 8 + 2 * l;
            int HW4 = 1 << lg4;
            int b = rem >> lg4;
            int pg = rem & (HW4 - 1);
            const float* src = fl[l] + (size_t)b * 8 * HW4;
            float4 vx = ((const float4*)src)[pg];
            float4 vy = ((const float4*)(src + 4 * HW4))[pg];
            float4* dst = (float4*)(g_fint + c_fioff[l] + b * 4 * HW4) + 2 * pg;
            dst[0] = make_float4(vx.x, vy.x, vx.y, vy.y);
            dst[1] = make_float4(vx.z, vy.z, vx.w, vy.w);
        }
    } else if (bid < 2 * PRE_Z + PRE_FI + 4) {
        int w = (bid - (2 * PRE_Z + PRE_FI)) * 8 + (tid >> 5);  // 0..31
        int lane = tid & 31;
        int b = w >> 2, m = (w >> 1) & 1, which = w & 1;
        int want = m ? -1 : 1;
        const int* pp = ps + b * NEV;
        const float* tt = ts + b * NEV;
        if (which == 0) {
            bool found = false;
            for (int base = 0; base < NEV && !found; base += 32) {
                int idx = base + lane;
                bool hit = (idx < NEV) && (pp[idx] == want);
                unsigned bal = __ballot_sync(0xffffffffu, hit);
                if (bal) {
                    if (lane == 0) g_tref[b][m][0] = tt[base + __ffs(bal) - 1];
                    found = true;
                }
            }
            if (!found && lane == 0) g_tref[b][m][0] = tt[0];
        } else {
            bool found = false;
            for (int base = NEV - 1; base >= 0 && !found; base -= 32) {
                int idx = base - lane;
                bool hit = (idx >= 0) && (pp[idx] == want);
                unsigned bal = __ballot_sync(0xffffffffu, hit);
                if (bal) {
                    if (lane == 0) g_tref[b][m][1] = tt[base - (__ffs(bal) - 1)];
                    found = true;
                }
            }
            if (!found && lane == 0) g_tref[b][m][1] = tt[NEV - 1];
        }
    } else {                                // ---- histogram ----
        int start = (bid - (2 * PRE_Z + PRE_FI + 4)) * 256 + tid;
        for (int i = start; i < B * NEV; i += PRE_HIST * 256) {
            int b = i / NEV;
            int m = (ps[i] == 1) ? 0 : 1;
            atomicAdd(&g_hist[ev_key(b, xs[i], ys[i], m)], 1);
        }
    }
}

// ---------------------------------------------------------------------------
// k_sort: blocks 0..7 = per-batch exclusive prefix over 8192 buckets -> g_cursor
//         blocks 8..  = gated scatter of packed events into g_sev
// ---------------------------------------------------------------------------
#define NB_SCAT 784
#define SORT_NB (8 + NB_SCAT)
__global__ void __launch_bounds__(256)
k_sort(const int* __restrict__ xs, const int* __restrict__ ys,
       const float* __restrict__ ts, const int* __restrict__ ps) {
    int bid = blockIdx.x, tid = threadIdx.x;
    if (bid < 8) {                          // ---- prefix scan (batch = bid) ----
        const int base = bid * NKEY;
        int vals[32];
        int s = 0;
#pragma unroll
        for (int j = 0; j < 32; j++) {
            vals[j] = g_hist[base + tid * 32 + j];
            s += vals[j];
        }
        __shared__ int warpsum[8];
        int lane = tid & 31, wid = tid >> 5;
        int inc = s;
        for (int o = 1; o < 32; o <<= 1) {
            int v = __shfl_up_sync(0xffffffffu, inc, o);
            if (lane >= o) inc += v;
        }
        if (lane == 31) warpsum[wid] = inc;
        __syncthreads();
        if (tid == 0) {
            int r = 0;
            for (int w = 0; w < 8; w++) { int t = warpsum[w]; warpsum[w] = r; r += t; }
        }
        __syncthreads();
        int run = bid * NEV + warpsum[wid] + (inc - s);   // exclusive prefix
#pragma unroll
        for (int j = 0; j < 32; j++) {
            g_cursor[base + tid * 32 + j] = run;
            run += vals[j];
        }
        gate_arrive(&g_cPfx);
    } else {                                // ---- scatter (gated) ----
        gate_wait(&g_cPfx, 8);
        int start = (bid - 8) * 256 + tid;
        for (int i = start; i < B * NEV; i += NB_SCAT * 256) {
            int b = i / NEV;
            int x = xs[i], y = ys[i];
            int m = (ps[i] == 1) ? 0 : 1;
            float t = ts[i];
            int pos = atomicAdd(&g_cursor[ev_key(b, x, y, m)], 1);
            g_sev[pos] = make_int2(x | (y << 8) | (m << 16), __float_as_int(t));
        }
    }
}

// ---------------------------------------------------------------------------
// Bilinear scatter. Even x0 -> v4 into A. Odd x0 (non-edge) -> v4 into B.
// Edge x0==W-1 -> v2 into A with summed weights (den +2, matching reference).
// ---------------------------------------------------------------------------
__device__ __forceinline__ void scatter(float2* __restrict__ imgA,
                                        float2* __restrict__ imgB, int W,
                                        float xl, float yl, float t_,
                                        float fx, float fy, float t) {
    float xf = fminf(fmaxf(fmaf(t_, fx, xl), 0.f), (float)(W - 1));
    float yf = fminf(fmaxf(fmaf(t_, fy, yl), 0.f), (float)(W - 1));
    float x0 = floorf(xf), y0 = floorf(yf);
    float x0w = xf - x0, y0w = yf - y0;
    float x1w = 1.f - x0w, y1w = 1.f - y0w;
    int x0i = (int)x0, y0i = (int)y0;
    int y1i = min(y0i + 1, W - 1);
    float nA = x1w * t;
    float nB = x0w * t;
    int p0 = y0i * W + x0i;
    int p1 = y1i * W + x0i;
    if (!(x0i & 1)) {
        red4(imgA + p0, nA * y1w, 1.f, nB * y1w, 1.f);
        red4(imgA + p1, nA * y0w, 1.f, nB * y0w, 1.f);
    } else if (x0i < W - 1) {
        red4(imgB + p0, nA * y1w, 1.f, nB * y1w, 1.f);
        red4(imgB + p1, nA * y0w, 1.f, nB * y0w, 1.f);
    } else {
        red2(imgA + p0, (nA + nB) * y1w, 2.f);
        red2(imgA + p1, (nA + nB) * y0w, 2.f);
    }
}

// ---------------------------------------------------------------------------
// k_main roles: [0,NB_SM) smoothness | rest events (sorted)
// ---------------------------------------------------------------------------
#define NB_EV 3125
__device__ __constant__ int c_smb[5] = {0, 384, 480, 504, 512};

__global__ void __launch_bounds__(256)
k_main(const float* __restrict__ f0, const float* __restrict__ f1,
       const float* __restrict__ f2, const float* __restrict__ f3) {
    int tid = threadIdx.x;
    if (blockIdx.x < NB_SM) {
        int l, b0, b1;
        if (blockIdx.x < c_smb[1])      { l = 3; b0 = c_smb[0]; b1 = c_smb[1]; }
        else if (blockIdx.x < c_smb[2]) { l = 2; b0 = c_smb[1]; b1 = c_smb[2]; }
        else if (blockIdx.x < c_smb[3]) { l = 1; b0 = c_smb[2]; b1 = c_smb[3]; }
        else                            { l = 0; b0 = c_smb[3]; b1 = c_smb[4]; }
        const float* f = (l == 3) ? f3 : (l == 2) ? f2 : (l == 1) ? f1 : f0;
        const int W = 32 << l;
        const int HW = W * W;
        const int n = 16 * HW;
        float inv_lr = 1.f / (16.f * W * (W - 1));
        float inv_d  = 1.f / (16.f * (W - 1) * (W - 1));
        int stride = (b1 - b0) * 256;
        float acc = 0.f;
        for (int i = (blockIdx.x - b0) * 256 + tid; i < n; i += stride) {
            int pix = i & (HW - 1);
            int col = pix & (W - 1);
            int row = pix >> (5 + l);
            float v = f[i];
            bool hr = (col < W - 1), hd = (row < W - 1);
            if (hr) {
                float r = f[i + 1];
                float d1 = r - v;
                acc += __powf(d1 * d1 + 1e-6f, 0.45f) * inv_lr;
                if (hd) {
                    float dn = f[i + W];
                    float dr = f[i + W + 1];
                    float t1 = dr - v;
                    float t2 = r - dn;
                    acc += (__powf(t1 * t1 + 1e-6f, 0.45f) +
                            __powf(t2 * t2 + 1e-6f, 0.45f)) * inv_d;
                }
            }
            if (hd) {
                float dn = f[i + W];
                float d2 = dn - v;
                acc += __powf(d2 * d2 + 1e-6f, 0.45f) * inv_lr;
            }
        }
        double s = block_reduce(acc);
        if (tid == 0) g_part_sm[blockIdx.x] = s;
    } else {
        int idx = (blockIdx.x - NB_SM) * 256 + tid;
        if (idx >= B * NEV) return;
        int b = idx / NEV;
        int2 e = g_sev[idx];
        int x = e.x & 255, y = (e.x >> 8) & 255, m = (e.x >> 16) & 1;
        float t = __int_as_float(e.y);
        float tfw = g_tref[b][m][1] - t + EPSF;
        float tbw = g_tref[b][m][0] - t - EPSF;
        int xl0 = x >> 3, yl0 = y >> 3;
        int xl1 = x >> 2, yl1 = y >> 2;
        int xl2 = x >> 1, yl2 = y >> 1;
        float2 fv0 = __ldg(g_fint + c_fioff[0] + b * 1024  + yl0 * 32  + xl0);
        float2 fv1 = __ldg(g_fint + c_fioff[1] + b * 4096  + yl1 * 64  + xl1);
        float2 fv2 = __ldg(g_fint + c_fioff[2] + b * 16384 + yl2 * 128 + xl2);
        float2 fv3 = __ldg(g_fint + c_fioff[3] + b * 65536 + y   * 256 + x);
        float2 fvs[4] = {fv0, fv1, fv2, fv3};
        int xls[4] = {xl0, xl1, xl2, x};
        int yls[4] = {yl0, yl1, yl2, y};
#pragma unroll
        for (int l = 0; l < 4; l++) {
            const int W = 32 << l;
            const int HW = W * W;
            int offF = c_loff[l] + ((b * 2 + 1) * 2 + m) * HW;
            int offB = c_loff[l] + ((b * 2 + 0) * 2 + m) * HW;
            scatter(g_accum + offF, g_accumB + 1 + offF, W,
                    (float)xls[l], (float)yls[l], tfw, fvs[l].x, fvs[l].y, t);
            scatter(g_accum + offB, g_accumB + 1 + offB, W,
                    (float)xls[l], (float)yls[l], tbw, fvs[l].x, fvs[l].y, t);
        }
    }
}

// ---------------------------------------------------------------------------
// k_post: ER(1024) | WD(256) | hist-zero(16). Last arriver writes out.
// ---------------------------------------------------------------------------
#define NB_POST (NB_ER + NB_WD + NB_HZ)
#define FIN_ARRIVALS NB_POST

__device__ __forceinline__ float ev_pair(float n0, float d0_, float n1, float d1_) {
    float d0 = d0_ + EPSF, d1 = d1_ + EPSF;
    float d0s = d0 * d0,   d1s = d1 * d1;
    float h0 = fmaf(n0, n0, 1e-6f * d0s);
    float h1 = fmaf(n1, n1, 1e-6f * d1s);
    return h0 * rsqrt_approx(h0 * d0s) + h1 * rsqrt_approx(h1 * d1s);
}

__global__ void __launch_bounds__(256)
k_post(const float* __restrict__ params, float* __restrict__ out) {
    if (blockIdx.x < NB_ER) {
        const float4* A4 = (const float4*)g_accum;
        const float4* B4 = (const float4*)g_accumB;
        const int n4 = ACCUM_F2 / 2;
        float a0 = 0.f, a1 = 0.f, a2 = 0.f, a3 = 0.f;
        for (int base = blockIdx.x * 1024 + threadIdx.x; base < n4; base += NB_ER * 1024) {
            int i1 = base + 256, i2 = base + 512, i3 = base + 768;
            bool g1 = i1 < n4, g2 = i2 < n4, g3 = i3 < n4;
            float4 va0 = A4[base], vb0 = B4[base], vc0 = B4[base + 1];
            float4 va1, vb1, vc1, va2, vb2, vc2, va3, vb3, vc3;
            if (g1) { va1 = A4[i1]; vb1 = B4[i1]; vc1 = B4[i1 + 1]; }
            if (g2) { va2 = A4[i2]; vb2 = B4[i2]; vc2 = B4[i2 + 1]; }
            if (g3) { va3 = A4[i3]; vb3 = B4[i3]; vc3 = B4[i3 + 1]; }
            a0 += ev_pair(va0.x + vb0.z, va0.y + vb0.w, va0.z + vc0.x, va0.w + vc0.y);
            if (g1) a1 += ev_pair(va1.x + vb1.z, va1.y + vb1.w, va1.z + vc1.x, va1.w + vc1.y);
            if (g2) a2 += ev_pair(va2.x + vb2.z, va2.y + vb2.w, va2.z + vc2.x, va2.w + vc2.y);
            if (g3) a3 += ev_pair(va3.x + vb3.z, va3.y + vb3.w, va3.z + vc3.x, va3.w + vc3.y);
        }
        double s = block_reduce((a0 + a1) + (a2 + a3));
        if (threadIdx.x == 0) g_part_er[blockIdx.x] = s;
    } else if (blockIdx.x < NB_ER + NB_WD) {
        const float4* p4 = (const float4*)params;
        const int n4 = NPARAMS / 4;
        float a0 = 0.f, a1 = 0.f, a2 = 0.f, a3 = 0.f;
        for (int base = (blockIdx.x - NB_ER) * 1024 + threadIdx.x; base < n4;
             base += NB_WD * 1024) {
            int i1 = base + 256, i2 = base + 512, i3 = base + 768;
            float4 v0 = p4[base];
            float4 v1 = (i1 < n4) ? p4[i1] : make_float4(0.f, 0.f, 0.f, 0.f);
            float4 v2 = (i2 < n4) ? p4[i2] : make_float4(0.f, 0.f, 0.f, 0.f);
            float4 v3 = (i3 < n4) ? p4[i3] : make_float4(0.f, 0.f, 0.f, 0.f);
            a0 += v0.x * v0.x + v0.y * v0.y + v0.z * v0.z + v0.w * v0.w;
            a1 += v1.x * v1.x + v1.y * v1.y + v1.z * v1.z + v1.w * v1.w;
            a2 += v2.x * v2.x + v2.y * v2.y + v2.z * v2.z + v2.w * v2.w;
            a3 += v3.x * v3.x + v3.y * v3.y + v3.z * v3.z + v3.w * v3.w;
        }
        double s = block_reduce((a0 + a1) + (a2 + a3));
        if (threadIdx.x == 0) g_part_wd[blockIdx.x - NB_ER] = s;
    } else {                                // ---- re-zero histogram ----
        int4* h4 = (int4*)g_hist;
        const int n = HIST_TOT / 4;
        for (int i = (blockIdx.x - NB_ER - NB_WD) * 256 + threadIdx.x; i < n;
             i += NB_HZ * 256)
            h4[i] = make_int4(0, 0, 0, 0);
    }

    __shared__ bool is_last;
    if (threadIdx.x == 0) {
        __threadfence();
        unsigned r = atomicAdd(&g_done, 1u);
        is_last = (r == FIN_ARRIVALS - 1);
    }
    __syncthreads();
    if (is_last) {
        __threadfence();
        __shared__ double swarp[8];
        double tot = 0.0;
        for (int i = threadIdx.x; i < NB_ER; i += 256) tot += g_part_er[i];
        for (int i = threadIdx.x; i < NB_SM; i += 256) tot += 6.25 * g_part_sm[i];
        for (int i = threadIdx.x; i < NB_WD; i += 256) tot += 5.0e-5 * g_part_wd[i];
        for (int o = 16; o > 0; o >>= 1) tot += __shfl_down_sync(0xffffffffu, tot, o);
        if ((threadIdx.x & 31) == 0) swarp[threadIdx.x >> 5] = tot;
        __syncthreads();
        if (threadIdx.x == 0) {
            double r = 0.0;
            for (int w = 0; w < 8; w++) r += swarp[w];
            out[0] = (float)r;
        }
    }
}

// ---------------------------------------------------------------------------
extern "C" void kernel_launch(void* const* d_in, const int* in_sizes, int n_in,
                              void* d_out, int out_size) {
    const float* f0 = (const float*)d_in[0];
    const float* f1 = (const float*)d_in[1];
    const float* f2 = (const float*)d_in[2];
    const float* f3 = (const float*)d_in[3];
    const int*   xs = (const int*)d_in[4];
    const int*   ys = (const int*)d_in[5];
    const float* ts = (const float*)d_in[6];
    const int*   ps = (const int*)d_in[7];
    const float* params = (const float*)d_in[10];
    float* out = (float*)d_out;

    k_pre<<<PRE_NB, 256>>>(f0, f1, f2, f3, ts, ps, xs, ys);
    k_sort<<<SORT_NB, 256>>>(xs, ys, ts, ps);
    k_main<<<NB_SM + NB_EV, 256>>>(f0, f1, f2, f3);
    k_post<<<NB_POST, 256>>>(params, out);
}

// round 17
// speedup vs baseline: 1.2547x; 1.2547x over previous
#include <cuda_runtime.h>
#include <math.h>

#define B 8
#define NEV 100000
#define NPARAMS 4000000
#define EPSF 1.1920928955078125e-07f

// Twin accumulators, float2 per pixel (x=num, y=den).
// A: pixel p at slot p. B: pixel p at slot p+1 (8-byte shift) so that ODD
// pixel pairs (x0,x0+1) are 16B-aligned in B -> always red.v4.
#define ACCUM_F2 2785280
__device__ __align__(16) float2 g_accum [ACCUM_F2];
__device__ __align__(16) float2 g_accumB[ACCUM_F2 + 2];
__device__ float g_tref[B][2][2];       // [b][m][0]=first(bwd), [1]=last(fwd)

// Interleaved flow (fx,fy) per pixel: level offsets (float2 units)
#define FI_TOT 696320
__device__ __align__(16) float2 g_fint[FI_TOT];
__device__ __constant__ int c_fioff[4]  = {0, 8192, 40960, 172032};
__device__ __constant__ int c_fioff4[5] = {0, 2048, 10240, 43008, 174080};

#define NB_SM 512
#define NB_WD 256
#define NB_ER 1024
__device__ double g_part_sm[NB_SM];
__device__ double g_part_wd[NB_WD];
__device__ double g_part_er[NB_ER];
__device__ unsigned g_done;

__device__ __constant__ int c_loff[4] = {0, 32768, 163840, 688128};

// ---------------------------------------------------------------------------
__device__ __forceinline__ void red4(float2* addr, float a, float b, float c, float d) {
    asm volatile("red.global.add.v4.f32 [%0], {%1,%2,%3,%4};" ::
                 "l"(addr), "f"(a), "f"(b), "f"(c), "f"(d));
}
__device__ __forceinline__ void red2(float2* addr, float a, float b) {
    asm volatile("red.global.add.v2.f32 [%0], {%1,%2};" ::
                 "l"(addr), "f"(a), "f"(b));
}
__device__ __forceinline__ float rsqrt_approx(float x) {
    float r;
    asm("rsqrt.approx.f32 %0, %1;" : "=f"(r) : "f"(x));
    return r;
}

// ---------------------------------------------------------------------------
__device__ __forceinline__ double block_reduce(float acc) {
    __shared__ double swarp[8];
    for (int o = 16; o > 0; o >>= 1) acc += __shfl_down_sync(0xffffffffu, acc, o);
    int wid = threadIdx.x >> 5, lid = threadIdx.x & 31;
    if (lid == 0) swarp[wid] = (double)acc;
    __syncthreads();
    double s = 0.0;
    if (threadIdx.x == 0)
        for (int w = 0; w < 8; w++) s += swarp[w];
    return s;
}

// ---------------------------------------------------------------------------
// k_pre roles: zero A (512) | zero B (512) | flow interleave (256, float4) |
// tref (4).
// ---------------------------------------------------------------------------
#define PRE_Z 512
#define PRE_FI 256
__global__ void __launch_bounds__(256)
k_pre(const float* __restrict__ f0, const float* __restrict__ f1,
      const float* __restrict__ f2, const float* __restrict__ f3,
      const float* __restrict__ ts, const int* __restrict__ ps) {
    int bid = blockIdx.x, tid = threadIdx.x;
    if (bid < PRE_Z) {
        if (bid == 0 && tid == 0) g_done = 0;
        float4* p = (float4*)g_accum;
        const int n = ACCUM_F2 / 2;
        for (int i = bid * 256 + tid; i < n; i += PRE_Z * 256)
            p[i] = make_float4(0.f, 0.f, 0.f, 0.f);
    } else if (bid < 2 * PRE_Z) {
        float4* p = (float4*)g_accumB;
        const int n = (ACCUM_F2 + 2) / 2;
        for (int i = (bid - PRE_Z) * 256 + tid; i < n; i += PRE_Z * 256)
            p[i] = make_float4(0.f, 0.f, 0.f, 0.f);
    } else if (bid < 2 * PRE_Z + PRE_FI) {
        const float* fl[4] = {f0, f1, f2, f3};
        const int n = c_fioff4[4];
        for (int i = (bid - 2 * PRE_Z) * 256 + tid; i < n; i += PRE_FI * 256) {
            int l = (i < c_fioff4[1]) ? 0 : (i < c_fioff4[2]) ? 1
                  : (i < c_fioff4[3]) ? 2 : 3;
            int rem = i - c_fioff4[l];
            int lg4 = 8 + 2 * l;
            int HW4 = 1 << lg4;
            int b = rem >> lg4;
            int pg = rem & (HW4 - 1);
            const float* src = fl[l] + (size_t)b * 8 * HW4;
            float4 vx = ((const float4*)src)[pg];
            float4 vy = ((const float4*)(src + 4 * HW4))[pg];
            float4* dst = (float4*)(g_fint + c_fioff[l] + b * 4 * HW4) + 2 * pg;
            dst[0] = make_float4(vx.x, vy.x, vx.y, vy.y);
            dst[1] = make_float4(vx.z, vy.z, vx.w, vy.w);
        }
    } else {
        int w = (bid - (2 * PRE_Z + PRE_FI)) * 8 + (tid >> 5);  // 0..31
        int lane = tid & 31;
        int b = w >> 2, m = (w >> 1) & 1, which = w & 1;
        int want = m ? -1 : 1;
        const int* pp = ps + b * NEV;
        const float* tt = ts + b * NEV;
        if (which == 0) {       // first matching (backward t_ref)
            bool found = false;
            for (int base = 0; base < NEV && !found; base += 32) {
                int idx = base + lane;
                bool hit = (idx < NEV) && (pp[idx] == want);
                unsigned bal = __ballot_sync(0xffffffffu, hit);
                if (bal) {
                    if (lane == 0) g_tref[b][m][0] = tt[base + __ffs(bal) - 1];
                    found = true;
                }
            }
            if (!found && lane == 0) g_tref[b][m][0] = tt[0];
        } else {                // last matching (forward t_ref)
            bool found = false;
            for (int base = NEV - 1; base >= 0 && !found; base -= 32) {
                int idx = base - lane;
                bool hit = (idx >= 0) && (pp[idx] == want);
                unsigned bal = __ballot_sync(0xffffffffu, hit);
                if (bal) {
                    if (lane == 0) g_tref[b][m][1] = tt[base - (__ffs(bal) - 1)];
                    found = true;
                }
            }
            if (!found && lane == 0) g_tref[b][m][1] = tt[NEV - 1];
        }
    }
}

// ---------------------------------------------------------------------------
// Bilinear scatter. Even x0 -> v4 into A. Odd x0 (non-edge) -> v4 into B.
// Edge x0==W-1 -> v2 into A with summed weights (den +2, matching reference).
// ---------------------------------------------------------------------------
__device__ __forceinline__ void scatter(float2* __restrict__ imgA,
                                        float2* __restrict__ imgB, int W,
                                        float xl, float yl, float t_,
                                        float fx, float fy, float t) {
    float xf = fminf(fmaxf(fmaf(t_, fx, xl), 0.f), (float)(W - 1));
    float yf = fminf(fmaxf(fmaf(t_, fy, yl), 0.f), (float)(W - 1));
    float x0 = floorf(xf), y0 = floorf(yf);
    float x0w = xf - x0, y0w = yf - y0;
    float x1w = 1.f - x0w, y1w = 1.f - y0w;
    int x0i = (int)x0, y0i = (int)y0;
    int y1i = min(y0i + 1, W - 1);
    float nA = x1w * t;
    float nB = x0w * t;
    int p0 = y0i * W + x0i;
    int p1 = y1i * W + x0i;
    if (!(x0i & 1)) {
        red4(imgA + p0, nA * y1w, 1.f, nB * y1w, 1.f);
        red4(imgA + p1, nA * y0w, 1.f, nB * y0w, 1.f);
    } else if (x0i < W - 1) {
        red4(imgB + p0, nA * y1w, 1.f, nB * y1w, 1.f);
        red4(imgB + p1, nA * y0w, 1.f, nB * y0w, 1.f);
    } else {
        red2(imgA + p0, (nA + nB) * y1w, 2.f);
        red2(imgA + p1, (nA + nB) * y0w, 2.f);
    }
}

// ---------------------------------------------------------------------------
// k_main roles: [0,NB_WD) weight decay | [NB_WD,+NB_SM) smoothness | rest events.
// WD is a pure DRAM stream riding under the L1tex-bound events.
// ---------------------------------------------------------------------------
#define NB_EV 3125
#define MB_WD   0
#define MB_SMO  NB_WD                 // 256
#define MB_EVT  (NB_WD + NB_SM)       // 768
__device__ __constant__ int c_smb[5] = {0, 384, 480, 504, 512};

__global__ void __launch_bounds__(256)
k_main(const float* __restrict__ f0, const float* __restrict__ f1,
       const float* __restrict__ f2, const float* __restrict__ f3,
       const int* __restrict__ xs, const int* __restrict__ ys,
       const float* __restrict__ ts, const int* __restrict__ ps,
       const float* __restrict__ params) {
    int tid = threadIdx.x;
    if (blockIdx.x < MB_SMO) {              // ---- weight decay ----
        const float4* p4 = (const float4*)params;
        const int n4 = NPARAMS / 4;
        float a0 = 0.f, a1 = 0.f, a2 = 0.f, a3 = 0.f;
        for (int base = blockIdx.x * 1024 + tid; base < n4; base += NB_WD * 1024) {
            int i1 = base + 256, i2 = base + 512, i3 = base + 768;
            float4 v0 = p4[base];
            float4 v1 = (i1 < n4) ? p4[i1] : make_float4(0.f, 0.f, 0.f, 0.f);
            float4 v2 = (i2 < n4) ? p4[i2] : make_float4(0.f, 0.f, 0.f, 0.f);
            float4 v3 = (i3 < n4) ? p4[i3] : make_float4(0.f, 0.f, 0.f, 0.f);
            a0 += v0.x * v0.x + v0.y * v0.y + v0.z * v0.z + v0.w * v0.w;
            a1 += v1.x * v1.x + v1.y * v1.y + v1.z * v1.z + v1.w * v1.w;
            a2 += v2.x * v2.x + v2.y * v2.y + v2.z * v2.z + v2.w * v2.w;
            a3 += v3.x * v3.x + v3.y * v3.y + v3.z * v3.z + v3.w * v3.w;
        }
        double s = block_reduce((a0 + a1) + (a2 + a3));
        if (tid == 0) g_part_wd[blockIdx.x] = s;
    } else if (blockIdx.x < MB_EVT) {       // ---- smoothness ----
        int sb = blockIdx.x - MB_SMO;
        int l, b0, b1;
        if (sb < c_smb[1])      { l = 3; b0 = c_smb[0]; b1 = c_smb[1]; }
        else if (sb < c_smb[2]) { l = 2; b0 = c_smb[1]; b1 = c_smb[2]; }
        else if (sb < c_smb[3]) { l = 1; b0 = c_smb[2]; b1 = c_smb[3]; }
        else                    { l = 0; b0 = c_smb[3]; b1 = c_smb[4]; }
        const float* f = (l == 3) ? f3 : (l == 2) ? f2 : (l == 1) ? f1 : f0;
        const int W = 32 << l;
        const int HW = W * W;
        const int n = 16 * HW;
        float inv_lr = 1.f / (16.f * W * (W - 1));
        float inv_d  = 1.f / (16.f * (W - 1) * (W - 1));
        int stride = (b1 - b0) * 256;
        float acc = 0.f;
        for (int i = (sb - b0) * 256 + tid; i < n; i += stride) {
            int pix = i & (HW - 1);
            int col = pix & (W - 1);
            int row = pix >> (5 + l);
            float v = f[i];
            bool hr = (col < W - 1), hd = (row < W - 1);
            if (hr) {
                float r = f[i + 1];
                float d1 = r - v;
                acc += __powf(d1 * d1 + 1e-6f, 0.45f) * inv_lr;
                if (hd) {
                    float dn = f[i + W];
                    float dr = f[i + W + 1];
                    float t1 = dr - v;
                    float t2 = r - dn;
                    acc += (__powf(t1 * t1 + 1e-6f, 0.45f) +
                            __powf(t2 * t2 + 1e-6f, 0.45f)) * inv_d;
                }
            }
            if (hd) {
                float dn = f[i + W];
                float d2 = dn - v;
                acc += __powf(d2 * d2 + 1e-6f, 0.45f) * inv_lr;
            }
        }
        double s = block_reduce(acc);
        if (tid == 0) g_part_sm[sb] = s;
    } else {                                // ---- events ----
        int idx = (blockIdx.x - MB_EVT) * 256 + tid;
        if (idx >= B * NEV) return;
        int b = idx / NEV;
        int x = xs[idx], y = ys[idx];
        float t = ts[idx];
        int m = (ps[idx] == 1) ? 0 : 1;
        float tfw = g_tref[b][m][1] - t + EPSF;
        float tbw = g_tref[b][m][0] - t - EPSF;
        int xl0 = x >> 3, yl0 = y >> 3;
        int xl1 = x >> 2, yl1 = y >> 2;
        int xl2 = x >> 1, yl2 = y >> 1;
        float2 fv0 = __ldg(g_fint + c_fioff[0] + b * 1024  + yl0 * 32  + xl0);
        float2 fv1 = __ldg(g_fint + c_fioff[1] + b * 4096  + yl1 * 64  + xl1);
        float2 fv2 = __ldg(g_fint + c_fioff[2] + b * 16384 + yl2 * 128 + xl2);
        float2 fv3 = __ldg(g_fint + c_fioff[3] + b * 65536 + y   * 256 + x);
        float2 fvs[4] = {fv0, fv1, fv2, fv3};
        int xls[4] = {xl0, xl1, xl2, x};
        int yls[4] = {yl0, yl1, yl2, y};
#pragma unroll
        for (int l = 0; l < 4; l++) {
            const int W = 32 << l;
            const int HW = W * W;
            int offF = c_loff[l] + ((b * 2 + 1) * 2 + m) * HW;
            int offB = c_loff[l] + ((b * 2 + 0) * 2 + m) * HW;
            scatter(g_accum + offF, g_accumB + 1 + offF, W,
                    (float)xls[l], (float)yls[l], tfw, fvs[l].x, fvs[l].y, t);
            scatter(g_accum + offB, g_accumB + 1 + offB, W,
                    (float)xls[l], (float)yls[l], tbw, fvs[l].x, fvs[l].y, t);
        }
    }
}

// ---------------------------------------------------------------------------
// k_post: event reduction only (A+B merge, MLP-4) + fused final combine.
// Pixel p: num = A[p].x + Bslot[p+1].x, den = A[p].y + Bslot[p+1].y.
// ---------------------------------------------------------------------------
#define NB_POST NB_ER

__device__ __forceinline__ float ev_pair(float n0, float d0_, float n1, float d1_) {
    float d0 = d0_ + EPSF, d1 = d1_ + EPSF;
    float d0s = d0 * d0,   d1s = d1 * d1;
    float h0 = fmaf(n0, n0, 1e-6f * d0s);
    float h1 = fmaf(n1, n1, 1e-6f * d1s);
    return h0 * rsqrt_approx(h0 * d0s) + h1 * rsqrt_approx(h1 * d1s);
}

__global__ void __launch_bounds__(256)
k_post(float* __restrict__ out) {
    const float4* A4 = (const float4*)g_accum;
    const float4* B4 = (const float4*)g_accumB;
    const int n4 = ACCUM_F2 / 2;    // 1,392,640
    float a0 = 0.f, a1 = 0.f, a2 = 0.f, a3 = 0.f;
    for (int base = blockIdx.x * 1024 + threadIdx.x; base < n4; base += NB_ER * 1024) {
        int i1 = base + 256, i2 = base + 512, i3 = base + 768;
        bool g1 = i1 < n4, g2 = i2 < n4, g3 = i3 < n4;
        float4 va0 = A4[base], vb0 = B4[base], vc0 = B4[base + 1];
        float4 va1, vb1, vc1, va2, vb2, vc2, va3, vb3, vc3;
        if (g1) { va1 = A4[i1]; vb1 = B4[i1]; vc1 = B4[i1 + 1]; }
        if (g2) { va2 = A4[i2]; vb2 = B4[i2]; vc2 = B4[i2 + 1]; }
        if (g3) { va3 = A4[i3]; vb3 = B4[i3]; vc3 = B4[i3 + 1]; }
        a0 += ev_pair(va0.x + vb0.z, va0.y + vb0.w, va0.z + vc0.x, va0.w + vc0.y);
        if (g1) a1 += ev_pair(va1.x + vb1.z, va1.y + vb1.w, va1.z + vc1.x, va1.w + vc1.y);
        if (g2) a2 += ev_pair(va2.x + vb2.z, va2.y + vb2.w, va2.z + vc2.x, va2.w + vc2.y);
        if (g3) a3 += ev_pair(va3.x + vb3.z, va3.y + vb3.w, va3.z + vc3.x, va3.w + vc3.y);
    }
    double s = block_reduce((a0 + a1) + (a2 + a3));

    __shared__ bool is_last;
    if (threadIdx.x == 0) {
        g_part_er[blockIdx.x] = s;
        __threadfence();
        unsigned r = atomicAdd(&g_done, 1u);
        is_last = (r == NB_POST - 1);
    }
    __syncthreads();
    if (is_last) {
        __threadfence();
        __shared__ double swarp[8];
        double tot = 0.0;
        for (int i = threadIdx.x; i < NB_ER; i += 256) tot += g_part_er[i];
        for (int i = threadIdx.x; i < NB_SM; i += 256) tot += 6.25 * g_part_sm[i];
        for (int i = threadIdx.x; i < NB_WD; i += 256) tot += 5.0e-5 * g_part_wd[i];
        for (int o = 16; o > 0; o >>= 1) tot += __shfl_down_sync(0xffffffffu, tot, o);
        if ((threadIdx.x & 31) == 0) swarp[threadIdx.x >> 5] = tot;
        __syncthreads();
        if (threadIdx.x == 0) {
            double r = 0.0;
            for (int w = 0; w < 8; w++) r += swarp[w];
            out[0] = (float)r;
        }
    }
}

// ---------------------------------------------------------------------------
extern "C" void kernel_launch(void* const* d_in, const int* in_sizes, int n_in,
                              void* d_out, int out_size) {
    const float* f0 = (const float*)d_in[0];
    const float* f1 = (const float*)d_in[1];
    const float* f2 = (const float*)d_in[2];
    const float* f3 = (const float*)d_in[3];
    const int*   xs = (const int*)d_in[4];
    const int*   ys = (const int*)d_in[5];
    const float* ts = (const float*)d_in[6];
    const int*   ps = (const int*)d_in[7];
    const float* params = (const float*)d_in[10];
    float* out = (float*)d_out;

    k_pre<<<2 * PRE_Z + PRE_FI + 4, 256>>>(f0, f1, f2, f3, ts, ps);
    k_main<<<MB_EVT + NB_EV, 256>>>(f0, f1, f2, f3, xs, ys, ts, ps, params);
    k_post<<<NB_POST, 256>>>(out);
}